// round 6
// baseline (speedup 1.0000x reference)
#include <cuda_runtime.h>
#include <cuda_bf16.h>
#include <cstdint>
#include <cstddef>

#define S_LEN 2048
#define B_DIM 8
#define E_DIM 1024
#define M_TOT (S_LEN*B_DIM)      // 16384
#define CH    (B_DIM*E_DIM)      // 8192
#define NCHUNK 16
#define CLEN  (S_LEN/NCHUNK)     // 128

// ---------------- scratch (device globals; no allocation allowed) ------------
__device__ __nv_bfloat16 g_xk_hi[(size_t)M_TOT*E_DIM];
__device__ __nv_bfloat16 g_xk_lo[(size_t)M_TOT*E_DIM];
__device__ __nv_bfloat16 g_xv_hi[(size_t)M_TOT*E_DIM];
__device__ __nv_bfloat16 g_xv_lo[(size_t)M_TOT*E_DIM];
__device__ __nv_bfloat16 g_r_hi [(size_t)M_TOT*E_DIM];
__device__ __nv_bfloat16 g_r_lo [(size_t)M_TOT*E_DIM];
__device__ float g_k [(size_t)M_TOT*E_DIM];
__device__ float g_v [(size_t)M_TOT*E_DIM];
__device__ __nv_bfloat16 g_wkt_hi[(size_t)E_DIM*E_DIM];
__device__ __nv_bfloat16 g_wkt_lo[(size_t)E_DIM*E_DIM];
__device__ __nv_bfloat16 g_wvt_hi[(size_t)E_DIM*E_DIM];
__device__ __nv_bfloat16 g_wvt_lo[(size_t)E_DIM*E_DIM];
__device__ __nv_bfloat16 g_wot_hi[(size_t)E_DIM*E_DIM];
__device__ __nv_bfloat16 g_wot_lo[(size_t)E_DIM*E_DIM];
__device__ float g_agg[3*NCHUNK*CH];
__device__ float g_pre[3*NCHUNK*CH];

// ---------------- helpers ----------------------------------------------------
__device__ __forceinline__ uint32_t smem_addr(const void* p) {
    uint32_t a;
    asm("{ .reg .u64 t; cvta.to.shared.u64 t, %1; cvt.u32.u64 %0, t; }" : "=r"(a) : "l"(p));
    return a;
}
#define CP_ASYNC16(dst, src) \
    asm volatile("cp.async.cg.shared.global [%0], [%1], 16;" :: "r"(dst), "l"(src) : "memory")
#define CP_COMMIT() asm volatile("cp.async.commit_group;" ::: "memory")
#define CP_WAIT(n)  asm volatile("cp.async.wait_group %0;" :: "n"(n) : "memory")

#define LDSM4(r, addr) \
    asm volatile("ldmatrix.sync.aligned.m8n8.x4.shared.b16 {%0,%1,%2,%3}, [%4];" \
        : "=r"((r)[0]), "=r"((r)[1]), "=r"((r)[2]), "=r"((r)[3]) : "r"(addr))

__device__ __forceinline__ void mma_bf16(float c[4], const uint32_t a[4], const uint32_t b[2]) {
    asm volatile(
        "mma.sync.aligned.m16n8k16.row.col.f32.bf16.bf16.f32 "
        "{%0,%1,%2,%3}, {%4,%5,%6,%7}, {%8,%9}, {%0,%1,%2,%3};\n"
        : "+f"(c[0]), "+f"(c[1]), "+f"(c[2]), "+f"(c[3])
        : "r"(a[0]), "r"(a[1]), "r"(a[2]), "r"(a[3]), "r"(b[0]), "r"(b[1]));
}

__device__ __forceinline__ void bsplit(float v, __nv_bfloat16& h, __nv_bfloat16& l) {
    h = __float2bfloat16_rn(v);
    l = __float2bfloat16_rn(v - __bfloat162float(h));
}

// ============================================================
// 1) token mix + bf16 split
// ============================================================
__global__ void mix_split_kernel(const float* __restrict__ x,
                                 const float* __restrict__ tmrkv) {
    int i4  = blockIdx.x * blockDim.x + threadIdx.x;
    int idx = i4 * 4;
    int e   = idx & (E_DIM - 1);
    float4 xc = *(const float4*)(x + idx);
    float4 xp = make_float4(0.f, 0.f, 0.f, 0.f);
    if (idx >= CH) xp = *(const float4*)(x + idx - CH);
    float4 mk = *(const float4*)(tmrkv + E_DIM   + e);
    float4 mv = *(const float4*)(tmrkv + 2*E_DIM + e);
    float ok[4], ov[4];
    ok[0] = mk.x*xc.x + (1.f-mk.x)*xp.x;  ov[0] = mv.x*xc.x + (1.f-mv.x)*xp.x;
    ok[1] = mk.y*xc.y + (1.f-mk.y)*xp.y;  ov[1] = mv.y*xc.y + (1.f-mv.y)*xp.y;
    ok[2] = mk.z*xc.z + (1.f-mk.z)*xp.z;  ov[2] = mv.z*xc.z + (1.f-mv.z)*xp.z;
    ok[3] = mk.w*xc.w + (1.f-mk.w)*xp.w;  ov[3] = mv.w*xc.w + (1.f-mv.w)*xp.w;
    ushort4 kh, kl, vh, vl;
    __nv_bfloat16 h, l;
    bsplit(ok[0], h, l); kh.x = __bfloat16_as_ushort(h); kl.x = __bfloat16_as_ushort(l);
    bsplit(ok[1], h, l); kh.y = __bfloat16_as_ushort(h); kl.y = __bfloat16_as_ushort(l);
    bsplit(ok[2], h, l); kh.z = __bfloat16_as_ushort(h); kl.z = __bfloat16_as_ushort(l);
    bsplit(ok[3], h, l); kh.w = __bfloat16_as_ushort(h); kl.w = __bfloat16_as_ushort(l);
    bsplit(ov[0], h, l); vh.x = __bfloat16_as_ushort(h); vl.x = __bfloat16_as_ushort(l);
    bsplit(ov[1], h, l); vh.y = __bfloat16_as_ushort(h); vl.y = __bfloat16_as_ushort(l);
    bsplit(ov[2], h, l); vh.z = __bfloat16_as_ushort(h); vl.z = __bfloat16_as_ushort(l);
    bsplit(ov[3], h, l); vh.w = __bfloat16_as_ushort(h); vl.w = __bfloat16_as_ushort(l);
    *(ushort4*)((unsigned short*)g_xk_hi + idx) = kh;
    *(ushort4*)((unsigned short*)g_xk_lo + idx) = kl;
    *(ushort4*)((unsigned short*)g_xv_hi + idx) = vh;
    *(ushort4*)((unsigned short*)g_xv_lo + idx) = vl;
}

// ============================================================
// 2) weight transpose + split:  T[n][k] = split(W[k][n])
// ============================================================
__global__ void wsplit_kernel(const float* __restrict__ W,
                              __nv_bfloat16* __restrict__ Thi,
                              __nv_bfloat16* __restrict__ Tlo) {
    __shared__ float t[32][33];
    int bx = blockIdx.x * 32;   // n block
    int by = blockIdx.y * 32;   // k block
    int tx = threadIdx.x;
    for (int j = threadIdx.y; j < 32; j += 8)
        t[j][tx] = W[(size_t)(by + j) * E_DIM + bx + tx];
    __syncthreads();
    for (int j = threadIdx.y; j < 32; j += 8) {
        float v = t[tx][j];           // element (k=by+tx, n=bx+j)
        __nv_bfloat16 h, l; bsplit(v, h, l);
        size_t o = (size_t)(bx + j) * E_DIM + by + tx;
        Thi[o] = h; Tlo[o] = l;
    }
}

// ============================================================
// 3) split-bf16 GEMM: m16n8k16 + ldmatrix + XOR-swizzle + 3-stage, 1 sync/iter
//    A: [M,K] bf16 hi/lo (K-major); B: [N,K] bf16 hi/lo (pre-transposed W)
//    smem tile: 128 rows x 64B, chunk swizzle c ^ ((row>>1)&3)
// ============================================================
#define BM 128
#define BN 128
#define BK 32
#define TILE_B 8192                // 128 * 64 bytes per operand tile
#define STAGE_B (4*TILE_B)         // Ah,Al,Bh,Bl = 32768
#define NSTG 3
#define GEMM_SMEM (NSTG*STAGE_B)   // 98304 -> 2 CTAs/SM

__global__ void __launch_bounds__(256)
gemm_bf16_split(const __nv_bfloat16* __restrict__ Ahi, const __nv_bfloat16* __restrict__ Alo,
                const __nv_bfloat16* __restrict__ Bhi, const __nv_bfloat16* __restrict__ Blo,
                float* __restrict__ C) {
    extern __shared__ uint32_t smem[];   // [NSTG][4][2048]

    int tid  = threadIdx.x;
    int warp = tid >> 5, lane = tid & 31;
    int wm = warp & 3, wn = warp >> 2;             // 4 x 2 warps
    int bm = blockIdx.y * BM, bn = blockIdx.x * BN;

    const char* srcs[4] = {
        (const char*)(Ahi + (size_t)bm * E_DIM),
        (const char*)(Alo + (size_t)bm * E_DIM),
        (const char*)(Bhi + (size_t)bn * E_DIM),
        (const char*)(Blo + (size_t)bn * E_DIM) };
    uint32_t sbase = smem_addr(smem);

    auto load_tile = [&](int kt, int stg) {
        uint32_t dst0 = sbase + (uint32_t)stg * STAGE_B;
        int koff = kt * (BK*2);    // byte offset along K
        #pragma unroll
        for (int arr = 0; arr < 4; arr++) {
            #pragma unroll
            for (int i = 0; i < 2; i++) {
                int f = tid + i*256;
                int row = f >> 2, ch = f & 3;
                int sw = ch ^ ((row >> 1) & 3);
                uint32_t dst = dst0 + arr*TILE_B + row*64 + sw*16;
                const char* src = srcs[arr] + (size_t)row * (E_DIM*2) + koff + ch*16;
                CP_ASYNC16(dst, src);
            }
        }
    };

    // ---- ldmatrix lane addresses (ks=0; ks=1 is XOR 32) ----
    int lm = lane & 7, lg = lane >> 3;   // lg = matrix index 0..3
    uint32_t aoff[2];
    #pragma unroll
    for (int mt = 0; mt < 2; mt++) {
        int row = wm*32 + mt*16 + (lg & 1)*8 + lm;
        int c0  = lg >> 1;                       // k-chunk bit0
        int swc = c0 ^ ((row >> 1) & 3);         // 2-bit swizzled chunk (ks=0)
        aoff[mt] = (uint32_t)(row*64 + swc*16);
    }
    uint32_t boff[4];
    #pragma unroll
    for (int j = 0; j < 4; j++) {
        int row = wn*64 + j*16 + (lg >> 1)*8 + lm;
        int c0  = lg & 1;
        int swc = c0 ^ ((row >> 1) & 3);
        boff[j] = (uint32_t)(row*64 + swc*16);
    }

    float acc[2][8][4];
    #pragma unroll
    for (int mt = 0; mt < 2; mt++)
        #pragma unroll
        for (int nt = 0; nt < 8; nt++)
            #pragma unroll
            for (int q = 0; q < 4; q++) acc[mt][nt][q] = 0.f;

    const int NK = E_DIM / BK;   // 32
    load_tile(0, 0); CP_COMMIT();
    load_tile(1, 1); CP_COMMIT();

    for (int kt = 0; kt < NK; kt++) {
        int stg = kt % NSTG;
        if (kt == NK - 1) { CP_WAIT(0); } else { CP_WAIT(1); }
        __syncthreads();   // stage kt visible to all; all warps done with stage kt-1
        if (kt + 2 < NK) { load_tile(kt + 2, (kt + 2) % NSTG); CP_COMMIT(); }

        uint32_t tAh = sbase + (uint32_t)stg * STAGE_B;
        uint32_t tAl = tAh + TILE_B;
        uint32_t tBh = tAh + 2*TILE_B;
        uint32_t tBl = tAh + 3*TILE_B;

        #pragma unroll
        for (int ks = 0; ks < 2; ks++) {
            uint32_t ksx = (uint32_t)(ks * 32);  // flips k-chunk bit1 (XOR-safe under swizzle)
            uint32_t ah[2][4], al[2][4], bh[8][2], bl[8][2];
            #pragma unroll
            for (int mt = 0; mt < 2; mt++) {
                LDSM4(ah[mt], tAh + (aoff[mt] ^ ksx));
                LDSM4(al[mt], tAl + (aoff[mt] ^ ksx));
            }
            #pragma unroll
            for (int j = 0; j < 4; j++) {
                uint32_t rb[4], rl[4];
                LDSM4(rb, tBh + (boff[j] ^ ksx));
                bh[2*j][0] = rb[0]; bh[2*j][1] = rb[1];
                bh[2*j+1][0] = rb[2]; bh[2*j+1][1] = rb[3];
                LDSM4(rl, tBl + (boff[j] ^ ksx));
                bl[2*j][0] = rl[0]; bl[2*j][1] = rl[1];
                bl[2*j+1][0] = rl[2]; bl[2*j+1][1] = rl[3];
            }
            #pragma unroll
            for (int mt = 0; mt < 2; mt++)
                #pragma unroll
                for (int nt = 0; nt < 8; nt++) {
                    mma_bf16(acc[mt][nt], ah[mt], bh[nt]);
                    mma_bf16(acc[mt][nt], ah[mt], bl[nt]);
                    mma_bf16(acc[mt][nt], al[mt], bh[nt]);
                }
        }
    }

    #pragma unroll
    for (int mt = 0; mt < 2; mt++) {
        int r0 = bm + wm*32 + mt*16 + (lane >> 2);
        #pragma unroll
        for (int nt = 0; nt < 8; nt++) {
            int c0 = bn + wn*64 + nt*8 + ((lane & 3) << 1);
            *(float2*)(&C[(size_t) r0     *E_DIM + c0]) = make_float2(acc[mt][nt][0], acc[mt][nt][1]);
            *(float2*)(&C[(size_t)(r0 + 8)*E_DIM + c0]) = make_float2(acc[mt][nt][2], acc[mt][nt][3]);
        }
    }
}

// ============================================================
// 4) chunked associative exp-scan
// ============================================================
__global__ void scan_pass1(const float* __restrict__ time_decay) {
    int tid = blockIdx.x * blockDim.x + threadIdx.x;
    int c = tid / CH, ch = tid % CH;
    float w = time_decay[ch & (E_DIM - 1)];
    float a = 0.f, b = 0.f, p = -1e30f;
    int base = c * CLEN;
    for (int t0 = 0; t0 < CLEN; t0 += 8) {
        float kk[8], vv[8];
        #pragma unroll
        for (int i = 0; i < 8; i++) {
            size_t off = (size_t)(base + t0 + i) * CH + ch;
            kk[i] = g_k[off]; vv[i] = g_v[off];
        }
        #pragma unroll
        for (int i = 0; i < 8; i++) {
            float pw = p + w;
            float d  = pw - kk[i];
            float e  = __expf(-fabsf(d));
            float e1 = (d >= 0.f) ? 1.f : e;
            float e2 = (d >= 0.f) ? e   : 1.f;
            a = a*e1 + vv[i]*e2;
            b = b*e1 + e2;
            p = fmaxf(pw, kk[i]);
        }
    }
    g_agg[              c*CH + ch] = a;
    g_agg[  NCHUNK*CH + c*CH + ch] = b;
    g_agg[2*NCHUNK*CH + c*CH + ch] = p;
}

__global__ void scan_pass2(const float* __restrict__ time_decay) {
    int ch = blockIdx.x * blockDim.x + threadIdx.x;
    float w  = time_decay[ch & (E_DIM - 1)];
    float Lw = (float)CLEN * w;
    float a = 0.f, b = 0.f, p = -1e30f;
    for (int c = 0; c < NCHUNK; c++) {
        g_pre[              c*CH + ch] = a;
        g_pre[  NCHUNK*CH + c*CH + ch] = b;
        g_pre[2*NCHUNK*CH + c*CH + ch] = p;
        float a2 = g_agg[              c*CH + ch];
        float b2 = g_agg[  NCHUNK*CH + c*CH + ch];
        float p2 = g_agg[2*NCHUNK*CH + c*CH + ch];
        float pw = p + Lw;
        float d  = pw - p2;
        float e  = __expf(-fabsf(d));
        float e1 = (d >= 0.f) ? 1.f : e;
        float e2 = (d >= 0.f) ? e   : 1.f;
        a = a*e1 + a2*e2;
        b = b*e1 + b2*e2;
        p = fmaxf(pw, p2);
    }
}

__global__ void scan_pass3(const float* __restrict__ time_decay,
                           const float* __restrict__ time_first) {
    int tid = blockIdx.x * blockDim.x + threadIdx.x;
    int c = tid / CH, ch = tid % CH;
    int e0 = ch & (E_DIM - 1);
    float w = time_decay[e0];
    float u = time_first[e0];
    float a = g_pre[              c*CH + ch];
    float b = g_pre[  NCHUNK*CH + c*CH + ch];
    float p = g_pre[2*NCHUNK*CH + c*CH + ch];
    int base = c * CLEN;
    for (int t0 = 0; t0 < CLEN; t0 += 8) {
        float kk[8], vv[8];
        #pragma unroll
        for (int i = 0; i < 8; i++) {
            size_t off = (size_t)(base + t0 + i) * CH + ch;
            kk[i] = g_k[off]; vv[i] = g_v[off];
        }
        #pragma unroll
        for (int i = 0; i < 8; i++) {
            float pw = p + w;
            float d  = pw - kk[i];
            float e  = __expf(-fabsf(d));
            float e1 = (d >= 0.f) ? 1.f : e;
            float e2 = (d >= 0.f) ? e   : 1.f;
            a = a*e1 + vv[i]*e2;
            b = b*e1 + e2;
            p = fmaxf(pw, kk[i]);
            float kb = kk[i] + u + w;
            float d2 = p - kb;
            float eo = __expf(-fabsf(d2));
            float o1 = (d2 >= 0.f) ? 1.f : eo;
            float o2 = (d2 >= 0.f) ? eo  : 1.f;
            float cn = a*o1 + vv[i]*o2;
            float dn = b*o1 + o2;
            float q  = __fdividef(cn, dn);
            size_t off = (size_t)(base + t0 + i) * CH + ch;
            __nv_bfloat16 h, l; bsplit(q, h, l);
            g_r_hi[off] = h; g_r_lo[off] = l;
        }
    }
}

// ============================================================
// launch
// ============================================================
extern "C" void kernel_launch(void* const* d_in, const int* in_sizes, int n_in,
                              void* d_out, int out_size) {
    const float* x     = (const float*)d_in[0];
    const float* tmrkv = (const float*)d_in[1];
    const float* Wk    = (const float*)d_in[2];
    const float* Wv    = (const float*)d_in[3];
    const float* td    = (const float*)d_in[4];
    const float* tf    = (const float*)d_in[5];
    const float* Wout  = (const float*)d_in[6];
    float* out = (float*)d_out;

    cudaFuncSetAttribute(gemm_bf16_split,
                         cudaFuncAttributeMaxDynamicSharedMemorySize, GEMM_SMEM);

    __nv_bfloat16 *p_xk_hi, *p_xk_lo, *p_xv_hi, *p_xv_lo, *p_r_hi, *p_r_lo;
    __nv_bfloat16 *p_wk_hi, *p_wk_lo, *p_wv_hi, *p_wv_lo, *p_wo_hi, *p_wo_lo;
    float *p_k, *p_v;
    cudaGetSymbolAddress((void**)&p_xk_hi, g_xk_hi);
    cudaGetSymbolAddress((void**)&p_xk_lo, g_xk_lo);
    cudaGetSymbolAddress((void**)&p_xv_hi, g_xv_hi);
    cudaGetSymbolAddress((void**)&p_xv_lo, g_xv_lo);
    cudaGetSymbolAddress((void**)&p_r_hi,  g_r_hi);
    cudaGetSymbolAddress((void**)&p_r_lo,  g_r_lo);
    cudaGetSymbolAddress((void**)&p_wk_hi, g_wkt_hi);
    cudaGetSymbolAddress((void**)&p_wk_lo, g_wkt_lo);
    cudaGetSymbolAddress((void**)&p_wv_hi, g_wvt_hi);
    cudaGetSymbolAddress((void**)&p_wv_lo, g_wvt_lo);
    cudaGetSymbolAddress((void**)&p_wo_hi, g_wot_hi);
    cudaGetSymbolAddress((void**)&p_wo_lo, g_wot_lo);
    cudaGetSymbolAddress((void**)&p_k,  g_k);
    cudaGetSymbolAddress((void**)&p_v,  g_v);

    // 1) mix + split
    mix_split_kernel<<<(M_TOT*E_DIM/4)/256, 256>>>(x, tmrkv);

    // 2) weight transpose + split
    dim3 wgrid(32, 32), wblk(32, 8);
    wsplit_kernel<<<wgrid, wblk>>>(Wk,   p_wk_hi, p_wk_lo);
    wsplit_kernel<<<wgrid, wblk>>>(Wv,   p_wv_hi, p_wv_lo);
    wsplit_kernel<<<wgrid, wblk>>>(Wout, p_wo_hi, p_wo_lo);

    // 3) k = xk @ Wk ; v = xv @ Wv
    dim3 ggrid(E_DIM/BN, M_TOT/BM);
    gemm_bf16_split<<<ggrid, 256, GEMM_SMEM>>>(p_xk_hi, p_xk_lo, p_wk_hi, p_wk_lo, p_k);
    gemm_bf16_split<<<ggrid, 256, GEMM_SMEM>>>(p_xv_hi, p_xv_lo, p_wv_hi, p_wv_lo, p_v);

    // 4) scan
    scan_pass1<<<(NCHUNK*CH)/256, 256>>>(td);
    scan_pass2<<<CH/256, 256>>>(td);
    scan_pass3<<<(NCHUNK*CH)/256, 256>>>(td, tf);

    // 5) out = rwkv @ Wout
    gemm_bf16_split<<<ggrid, 256, GEMM_SMEM>>>(p_r_hi, p_r_lo, p_wo_hi, p_wo_lo, out);
}

// round 7
// speedup vs baseline: 1.5343x; 1.5343x over previous
#include <cuda_runtime.h>
#include <cuda_fp16.h>
#include <cstdint>
#include <cstddef>

#define S_LEN 2048
#define B_DIM 8
#define E_DIM 1024
#define M_TOT (S_LEN*B_DIM)      // 16384
#define CH    (B_DIM*E_DIM)      // 8192
#define NCHUNK 16
#define CLEN  (S_LEN/NCHUNK)     // 128

// ---------------- scratch (device globals; no allocation allowed) ------------
__device__ __half g_xk_hi[(size_t)M_TOT*E_DIM];
__device__ __half g_xk_lo[(size_t)M_TOT*E_DIM];
__device__ __half g_xv_hi[(size_t)M_TOT*E_DIM];
__device__ __half g_xv_lo[(size_t)M_TOT*E_DIM];
__device__ __half g_r_hi [(size_t)M_TOT*E_DIM];
__device__ __half g_r_lo [(size_t)M_TOT*E_DIM];
__device__ float g_k [(size_t)M_TOT*E_DIM];
__device__ float g_v [(size_t)M_TOT*E_DIM];
__device__ __half g_wkt[(size_t)E_DIM*E_DIM];
__device__ __half g_wvt[(size_t)E_DIM*E_DIM];
__device__ __half g_wot[(size_t)E_DIM*E_DIM];
__device__ float g_agg[3*NCHUNK*CH];
__device__ float g_pre[3*NCHUNK*CH];

// ---------------- helpers ----------------------------------------------------
__device__ __forceinline__ uint32_t smem_addr(const void* p) {
    uint32_t a;
    asm("{ .reg .u64 t; cvta.to.shared.u64 t, %1; cvt.u32.u64 %0, t; }" : "=r"(a) : "l"(p));
    return a;
}
#define CP_ASYNC16(dst, src) \
    asm volatile("cp.async.cg.shared.global [%0], [%1], 16;" :: "r"(dst), "l"(src) : "memory")
#define CP_COMMIT() asm volatile("cp.async.commit_group;" ::: "memory")
#define CP_WAIT(n)  asm volatile("cp.async.wait_group %0;" :: "n"(n) : "memory")

#define LDSM4(r, addr) \
    asm volatile("ldmatrix.sync.aligned.m8n8.x4.shared.b16 {%0,%1,%2,%3}, [%4];" \
        : "=r"((r)[0]), "=r"((r)[1]), "=r"((r)[2]), "=r"((r)[3]) : "r"(addr))

__device__ __forceinline__ void mma_f16(float c[4], const uint32_t a[4], const uint32_t b[2]) {
    asm volatile(
        "mma.sync.aligned.m16n8k16.row.col.f32.f16.f16.f32 "
        "{%0,%1,%2,%3}, {%4,%5,%6,%7}, {%8,%9}, {%0,%1,%2,%3};\n"
        : "+f"(c[0]), "+f"(c[1]), "+f"(c[2]), "+f"(c[3])
        : "r"(a[0]), "r"(a[1]), "r"(a[2]), "r"(a[3]), "r"(b[0]), "r"(b[1]));
}

__device__ __forceinline__ void hsplit(float v, __half& h, __half& l) {
    h = __float2half_rn(v);
    l = __float2half_rn(v - __half2float(h));
}

// ============================================================
// 1) token mix + fp16 split
// ============================================================
__global__ void mix_split_kernel(const float* __restrict__ x,
                                 const float* __restrict__ tmrkv) {
    int i4  = blockIdx.x * blockDim.x + threadIdx.x;
    int idx = i4 * 4;
    int e   = idx & (E_DIM - 1);
    float4 xc = *(const float4*)(x + idx);
    float4 xp = make_float4(0.f, 0.f, 0.f, 0.f);
    if (idx >= CH) xp = *(const float4*)(x + idx - CH);
    float4 mk = *(const float4*)(tmrkv + E_DIM   + e);
    float4 mv = *(const float4*)(tmrkv + 2*E_DIM + e);
    float ok[4], ov[4];
    ok[0] = mk.x*xc.x + (1.f-mk.x)*xp.x;  ov[0] = mv.x*xc.x + (1.f-mv.x)*xp.x;
    ok[1] = mk.y*xc.y + (1.f-mk.y)*xp.y;  ov[1] = mv.y*xc.y + (1.f-mv.y)*xp.y;
    ok[2] = mk.z*xc.z + (1.f-mk.z)*xp.z;  ov[2] = mv.z*xc.z + (1.f-mv.z)*xp.z;
    ok[3] = mk.w*xc.w + (1.f-mk.w)*xp.w;  ov[3] = mv.w*xc.w + (1.f-mv.w)*xp.w;
    ushort4 kh, kl, vh, vl;
    __half h, l;
    hsplit(ok[0], h, l); kh.x = __half_as_ushort(h); kl.x = __half_as_ushort(l);
    hsplit(ok[1], h, l); kh.y = __half_as_ushort(h); kl.y = __half_as_ushort(l);
    hsplit(ok[2], h, l); kh.z = __half_as_ushort(h); kl.z = __half_as_ushort(l);
    hsplit(ok[3], h, l); kh.w = __half_as_ushort(h); kl.w = __half_as_ushort(l);
    hsplit(ov[0], h, l); vh.x = __half_as_ushort(h); vl.x = __half_as_ushort(l);
    hsplit(ov[1], h, l); vh.y = __half_as_ushort(h); vl.y = __half_as_ushort(l);
    hsplit(ov[2], h, l); vh.z = __half_as_ushort(h); vl.z = __half_as_ushort(l);
    hsplit(ov[3], h, l); vh.w = __half_as_ushort(h); vl.w = __half_as_ushort(l);
    *(ushort4*)((unsigned short*)g_xk_hi + idx) = kh;
    *(ushort4*)((unsigned short*)g_xk_lo + idx) = kl;
    *(ushort4*)((unsigned short*)g_xv_hi + idx) = vh;
    *(ushort4*)((unsigned short*)g_xv_lo + idx) = vl;
}

// ============================================================
// 2) weight transpose + fp16 quantize:  T[n][k] = rn(W[k][n])
// ============================================================
__global__ void wsplit_kernel(const float* __restrict__ W,
                              __half* __restrict__ T) {
    __shared__ float t[32][33];
    int bx = blockIdx.x * 32;   // n block
    int by = blockIdx.y * 32;   // k block
    int tx = threadIdx.x;
    for (int j = threadIdx.y; j < 32; j += 8)
        t[j][tx] = W[(size_t)(by + j) * E_DIM + bx + tx];
    __syncthreads();
    for (int j = threadIdx.y; j < 32; j += 8) {
        float v = t[tx][j];           // element (k=by+tx, n=bx+j)
        T[(size_t)(bx + j) * E_DIM + by + tx] = __float2half_rn(v);
    }
}

// ============================================================
// 3) 2-product fp16 GEMM: C = (Ah+Al) @ Bq^T
//    m16n8k16 + ldmatrix + XOR swizzle + 3-stage cp.async, 1 sync/iter
// ============================================================
#define BM 128
#define BN 128
#define BK 32
#define TILE_B 8192                // 128 rows * 64 bytes per operand tile
#define STAGE_B (3*TILE_B)         // Ah, Al, Bq = 24576
#define NSTG 3
#define GEMM_SMEM (NSTG*STAGE_B)   // 73728 -> 2 CTAs/SM

__global__ void __launch_bounds__(256)
gemm_f16_2p(const __half* __restrict__ Ahi, const __half* __restrict__ Alo,
            const __half* __restrict__ Bq, float* __restrict__ C) {
    extern __shared__ uint32_t smem[];

    int tid  = threadIdx.x;
    int warp = tid >> 5, lane = tid & 31;
    int wm = warp & 3, wn = warp >> 2;             // 4 x 2 warps
    int bm = blockIdx.y * BM, bn = blockIdx.x * BN;

    const char* srcs[3] = {
        (const char*)(Ahi + (size_t)bm * E_DIM),
        (const char*)(Alo + (size_t)bm * E_DIM),
        (const char*)(Bq  + (size_t)bn * E_DIM) };
    uint32_t sbase = smem_addr(smem);

    auto load_tile = [&](int kt, int stg) {
        uint32_t dst0 = sbase + (uint32_t)stg * STAGE_B;
        int koff = kt * (BK*2);    // byte offset along K
        #pragma unroll
        for (int arr = 0; arr < 3; arr++) {
            #pragma unroll
            for (int i = 0; i < 2; i++) {
                int f = tid + i*256;
                int row = f >> 2, ch = f & 3;
                int sw = ch ^ ((row >> 1) & 3);
                uint32_t dst = dst0 + arr*TILE_B + row*64 + sw*16;
                const char* src = srcs[arr] + (size_t)row * (E_DIM*2) + koff + ch*16;
                CP_ASYNC16(dst, src);
            }
        }
    };

    // ---- ldmatrix lane addresses (ks=0; ks=1 is XOR 32) ----
    int lm = lane & 7, lg = lane >> 3;   // lg = matrix index 0..3
    uint32_t aoff[2];
    #pragma unroll
    for (int mt = 0; mt < 2; mt++) {
        int row = wm*32 + mt*16 + (lg & 1)*8 + lm;
        int swc = (lg >> 1) ^ ((row >> 1) & 3);
        aoff[mt] = (uint32_t)(row*64 + swc*16);
    }
    uint32_t boff[4];
    #pragma unroll
    for (int j = 0; j < 4; j++) {
        int row = wn*64 + j*16 + (lg >> 1)*8 + lm;
        int swc = (lg & 1) ^ ((row >> 1) & 3);
        boff[j] = (uint32_t)(row*64 + swc*16);
    }

    float acc[2][8][4];
    #pragma unroll
    for (int mt = 0; mt < 2; mt++)
        #pragma unroll
        for (int nt = 0; nt < 8; nt++)
            #pragma unroll
            for (int q = 0; q < 4; q++) acc[mt][nt][q] = 0.f;

    const int NK = E_DIM / BK;   // 32
    load_tile(0, 0); CP_COMMIT();
    load_tile(1, 1); CP_COMMIT();

    for (int kt = 0; kt < NK; kt++) {
        int stg = kt % NSTG;
        if (kt == NK - 1) { CP_WAIT(0); } else { CP_WAIT(1); }
        __syncthreads();
        if (kt + 2 < NK) { load_tile(kt + 2, (kt + 2) % NSTG); CP_COMMIT(); }

        uint32_t tAh = sbase + (uint32_t)stg * STAGE_B;
        uint32_t tAl = tAh + TILE_B;
        uint32_t tB  = tAh + 2*TILE_B;

        #pragma unroll
        for (int ks = 0; ks < 2; ks++) {
            uint32_t ksx = (uint32_t)(ks * 32);
            uint32_t ah[2][4], al[2][4], bq[8][2];
            #pragma unroll
            for (int mt = 0; mt < 2; mt++) {
                LDSM4(ah[mt], tAh + (aoff[mt] ^ ksx));
                LDSM4(al[mt], tAl + (aoff[mt] ^ ksx));
            }
            #pragma unroll
            for (int j = 0; j < 4; j++) {
                uint32_t rb[4];
                LDSM4(rb, tB + (boff[j] ^ ksx));
                bq[2*j][0] = rb[0]; bq[2*j][1] = rb[1];
                bq[2*j+1][0] = rb[2]; bq[2*j+1][1] = rb[3];
            }
            #pragma unroll
            for (int mt = 0; mt < 2; mt++)
                #pragma unroll
                for (int nt = 0; nt < 8; nt++) {
                    mma_f16(acc[mt][nt], ah[mt], bq[nt]);
                    mma_f16(acc[mt][nt], al[mt], bq[nt]);
                }
        }
    }

    #pragma unroll
    for (int mt = 0; mt < 2; mt++) {
        int r0 = bm + wm*32 + mt*16 + (lane >> 2);
        #pragma unroll
        for (int nt = 0; nt < 8; nt++) {
            int c0 = bn + wn*64 + nt*8 + ((lane & 3) << 1);
            *(float2*)(&C[(size_t) r0     *E_DIM + c0]) = make_float2(acc[mt][nt][0], acc[mt][nt][1]);
            *(float2*)(&C[(size_t)(r0 + 8)*E_DIM + c0]) = make_float2(acc[mt][nt][2], acc[mt][nt][3]);
        }
    }
}

// ============================================================
// 4) chunked associative exp-scan
// ============================================================
__global__ void scan_pass1(const float* __restrict__ time_decay) {
    int tid = blockIdx.x * blockDim.x + threadIdx.x;
    int c = tid / CH, ch = tid % CH;
    float w = time_decay[ch & (E_DIM - 1)];
    float a = 0.f, b = 0.f, p = -1e30f;
    int base = c * CLEN;
    for (int t0 = 0; t0 < CLEN; t0 += 8) {
        float kk[8], vv[8];
        #pragma unroll
        for (int i = 0; i < 8; i++) {
            size_t off = (size_t)(base + t0 + i) * CH + ch;
            kk[i] = g_k[off]; vv[i] = g_v[off];
        }
        #pragma unroll
        for (int i = 0; i < 8; i++) {
            float pw = p + w;
            float d  = pw - kk[i];
            float e  = __expf(-fabsf(d));
            float e1 = (d >= 0.f) ? 1.f : e;
            float e2 = (d >= 0.f) ? e   : 1.f;
            a = a*e1 + vv[i]*e2;
            b = b*e1 + e2;
            p = fmaxf(pw, kk[i]);
        }
    }
    g_agg[              c*CH + ch] = a;
    g_agg[  NCHUNK*CH + c*CH + ch] = b;
    g_agg[2*NCHUNK*CH + c*CH + ch] = p;
}

__global__ void scan_pass2(const float* __restrict__ time_decay) {
    int ch = blockIdx.x * blockDim.x + threadIdx.x;
    float w  = time_decay[ch & (E_DIM - 1)];
    float Lw = (float)CLEN * w;
    float a = 0.f, b = 0.f, p = -1e30f;
    for (int c = 0; c < NCHUNK; c++) {
        g_pre[              c*CH + ch] = a;
        g_pre[  NCHUNK*CH + c*CH + ch] = b;
        g_pre[2*NCHUNK*CH + c*CH + ch] = p;
        float a2 = g_agg[              c*CH + ch];
        float b2 = g_agg[  NCHUNK*CH + c*CH + ch];
        float p2 = g_agg[2*NCHUNK*CH + c*CH + ch];
        float pw = p + Lw;
        float d  = pw - p2;
        float e  = __expf(-fabsf(d));
        float e1 = (d >= 0.f) ? 1.f : e;
        float e2 = (d >= 0.f) ? e   : 1.f;
        a = a*e1 + a2*e2;
        b = b*e1 + b2*e2;
        p = fmaxf(pw, p2);
    }
}

__global__ void scan_pass3(const float* __restrict__ time_decay,
                           const float* __restrict__ time_first) {
    int tid = blockIdx.x * blockDim.x + threadIdx.x;
    int c = tid / CH, ch = tid % CH;
    int e0 = ch & (E_DIM - 1);
    float w = time_decay[e0];
    float u = time_first[e0];
    float a = g_pre[              c*CH + ch];
    float b = g_pre[  NCHUNK*CH + c*CH + ch];
    float p = g_pre[2*NCHUNK*CH + c*CH + ch];
    int base = c * CLEN;
    for (int t0 = 0; t0 < CLEN; t0 += 8) {
        float kk[8], vv[8];
        #pragma unroll
        for (int i = 0; i < 8; i++) {
            size_t off = (size_t)(base + t0 + i) * CH + ch;
            kk[i] = g_k[off]; vv[i] = g_v[off];
        }
        #pragma unroll
        for (int i = 0; i < 8; i++) {
            float pw = p + w;
            float d  = pw - kk[i];
            float e  = __expf(-fabsf(d));
            float e1 = (d >= 0.f) ? 1.f : e;
            float e2 = (d >= 0.f) ? e   : 1.f;
            a = a*e1 + vv[i]*e2;
            b = b*e1 + e2;
            p = fmaxf(pw, kk[i]);
            float kb = kk[i] + u + w;
            float d2 = p - kb;
            float eo = __expf(-fabsf(d2));
            float o1 = (d2 >= 0.f) ? 1.f : eo;
            float o2 = (d2 >= 0.f) ? eo  : 1.f;
            float cn = a*o1 + vv[i]*o2;
            float dn = b*o1 + o2;
            float q  = __fdividef(cn, dn);
            size_t off = (size_t)(base + t0 + i) * CH + ch;
            __half h, l; hsplit(q, h, l);
            g_r_hi[off] = h; g_r_lo[off] = l;
        }
    }
}

// ============================================================
// launch
// ============================================================
extern "C" void kernel_launch(void* const* d_in, const int* in_sizes, int n_in,
                              void* d_out, int out_size) {
    const float* x     = (const float*)d_in[0];
    const float* tmrkv = (const float*)d_in[1];
    const float* Wk    = (const float*)d_in[2];
    const float* Wv    = (const float*)d_in[3];
    const float* td    = (const float*)d_in[4];
    const float* tf    = (const float*)d_in[5];
    const float* Wout  = (const float*)d_in[6];
    float* out = (float*)d_out;

    cudaFuncSetAttribute(gemm_f16_2p,
                         cudaFuncAttributeMaxDynamicSharedMemorySize, GEMM_SMEM);

    __half *p_xk_hi, *p_xk_lo, *p_xv_hi, *p_xv_lo, *p_r_hi, *p_r_lo;
    __half *p_wk, *p_wv, *p_wo;
    float *p_k, *p_v;
    cudaGetSymbolAddress((void**)&p_xk_hi, g_xk_hi);
    cudaGetSymbolAddress((void**)&p_xk_lo, g_xk_lo);
    cudaGetSymbolAddress((void**)&p_xv_hi, g_xv_hi);
    cudaGetSymbolAddress((void**)&p_xv_lo, g_xv_lo);
    cudaGetSymbolAddress((void**)&p_r_hi,  g_r_hi);
    cudaGetSymbolAddress((void**)&p_r_lo,  g_r_lo);
    cudaGetSymbolAddress((void**)&p_wk, g_wkt);
    cudaGetSymbolAddress((void**)&p_wv, g_wvt);
    cudaGetSymbolAddress((void**)&p_wo, g_wot);
    cudaGetSymbolAddress((void**)&p_k,  g_k);
    cudaGetSymbolAddress((void**)&p_v,  g_v);

    // 1) mix + split
    mix_split_kernel<<<(M_TOT*E_DIM/4)/256, 256>>>(x, tmrkv);

    // 2) weight transpose + quantize
    dim3 wgrid(32, 32), wblk(32, 8);
    wsplit_kernel<<<wgrid, wblk>>>(Wk,   p_wk);
    wsplit_kernel<<<wgrid, wblk>>>(Wv,   p_wv);
    wsplit_kernel<<<wgrid, wblk>>>(Wout, p_wo);

    // 3) k = xk @ Wk ; v = xv @ Wv
    dim3 ggrid(E_DIM/BN, M_TOT/BM);
    gemm_f16_2p<<<ggrid, 256, GEMM_SMEM>>>(p_xk_hi, p_xk_lo, p_wk, p_k);
    gemm_f16_2p<<<ggrid, 256, GEMM_SMEM>>>(p_xv_hi, p_xv_lo, p_wv, p_v);

    // 4) scan
    scan_pass1<<<(NCHUNK*CH)/256, 256>>>(td);
    scan_pass2<<<CH/256, 256>>>(td);
    scan_pass3<<<(NCHUNK*CH)/256, 256>>>(td, tf);

    // 5) out = rwkv @ Wout
    gemm_f16_2p<<<ggrid, 256, GEMM_SMEM>>>(p_r_hi, p_r_lo, p_wo, out);
}

// round 8
// speedup vs baseline: 2.2941x; 1.4952x over previous
#include <cuda_runtime.h>
#include <cuda_fp16.h>
#include <cstdint>
#include <cstddef>

#define S_LEN 2048
#define B_DIM 8
#define E_DIM 1024
#define M_TOT (S_LEN*B_DIM)      // 16384
#define CH    (B_DIM*E_DIM)      // 8192
#define NCHUNK 32
#define CLEN  (S_LEN/NCHUNK)     // 64

// ---------------- scratch (device globals; no allocation allowed) ------------
__device__ __half g_xk[(size_t)M_TOT*E_DIM];
__device__ __half g_xv[(size_t)M_TOT*E_DIM];
__device__ __half g_r [(size_t)M_TOT*E_DIM];
__device__ float g_k [(size_t)M_TOT*E_DIM];
__device__ float g_v [(size_t)M_TOT*E_DIM];
__device__ __half g_wkt[(size_t)E_DIM*E_DIM];
__device__ __half g_wvt[(size_t)E_DIM*E_DIM];
__device__ __half g_wot[(size_t)E_DIM*E_DIM];
__device__ float g_agg[3*NCHUNK*CH];
__device__ float g_pre[3*NCHUNK*CH];

// ---------------- helpers ----------------------------------------------------
__device__ __forceinline__ uint32_t smem_addr(const void* p) {
    uint32_t a;
    asm("{ .reg .u64 t; cvta.to.shared.u64 t, %1; cvt.u32.u64 %0, t; }" : "=r"(a) : "l"(p));
    return a;
}
#define CP_ASYNC16(dst, src) \
    asm volatile("cp.async.cg.shared.global [%0], [%1], 16;" :: "r"(dst), "l"(src) : "memory")
#define CP_COMMIT() asm volatile("cp.async.commit_group;" ::: "memory")
#define CP_WAIT(n)  asm volatile("cp.async.wait_group %0;" :: "n"(n) : "memory")

#define LDSM4(r, addr) \
    asm volatile("ldmatrix.sync.aligned.m8n8.x4.shared.b16 {%0,%1,%2,%3}, [%4];" \
        : "=r"((r)[0]), "=r"((r)[1]), "=r"((r)[2]), "=r"((r)[3]) : "r"(addr))

__device__ __forceinline__ void mma_f16(float c[4], const uint32_t a[4], const uint32_t b[2]) {
    asm volatile(
        "mma.sync.aligned.m16n8k16.row.col.f32.f16.f16.f32 "
        "{%0,%1,%2,%3}, {%4,%5,%6,%7}, {%8,%9}, {%0,%1,%2,%3};\n"
        : "+f"(c[0]), "+f"(c[1]), "+f"(c[2]), "+f"(c[3])
        : "r"(a[0]), "r"(a[1]), "r"(a[2]), "r"(a[3]), "r"(b[0]), "r"(b[1]));
}

// ============================================================
// 1) token mix + fp16 quantize
// ============================================================
__global__ void mix_quant_kernel(const float* __restrict__ x,
                                 const float* __restrict__ tmrkv) {
    int i4  = blockIdx.x * blockDim.x + threadIdx.x;
    int idx = i4 * 4;
    int e   = idx & (E_DIM - 1);
    float4 xc = *(const float4*)(x + idx);
    float4 xp = make_float4(0.f, 0.f, 0.f, 0.f);
    if (idx >= CH) xp = *(const float4*)(x + idx - CH);
    float4 mk = *(const float4*)(tmrkv + E_DIM   + e);
    float4 mv = *(const float4*)(tmrkv + 2*E_DIM + e);
    float ok[4], ov[4];
    ok[0] = mk.x*xc.x + (1.f-mk.x)*xp.x;  ov[0] = mv.x*xc.x + (1.f-mv.x)*xp.x;
    ok[1] = mk.y*xc.y + (1.f-mk.y)*xp.y;  ov[1] = mv.y*xc.y + (1.f-mv.y)*xp.y;
    ok[2] = mk.z*xc.z + (1.f-mk.z)*xp.z;  ov[2] = mv.z*xc.z + (1.f-mv.z)*xp.z;
    ok[3] = mk.w*xc.w + (1.f-mk.w)*xp.w;  ov[3] = mv.w*xc.w + (1.f-mv.w)*xp.w;
    ushort4 kq, vq;
    kq.x = __half_as_ushort(__float2half_rn(ok[0]));
    kq.y = __half_as_ushort(__float2half_rn(ok[1]));
    kq.z = __half_as_ushort(__float2half_rn(ok[2]));
    kq.w = __half_as_ushort(__float2half_rn(ok[3]));
    vq.x = __half_as_ushort(__float2half_rn(ov[0]));
    vq.y = __half_as_ushort(__float2half_rn(ov[1]));
    vq.z = __half_as_ushort(__float2half_rn(ov[2]));
    vq.w = __half_as_ushort(__float2half_rn(ov[3]));
    *(ushort4*)((unsigned short*)g_xk + idx) = kq;
    *(ushort4*)((unsigned short*)g_xv + idx) = vq;
}

// ============================================================
// 2) weight transpose + fp16 quantize:  T[n][k] = rn(W[k][n])
// ============================================================
__global__ void wsplit_kernel(const float* __restrict__ W,
                              __half* __restrict__ T) {
    __shared__ float t[32][33];
    int bx = blockIdx.x * 32;   // n block
    int by = blockIdx.y * 32;   // k block
    int tx = threadIdx.x;
    for (int j = threadIdx.y; j < 32; j += 8)
        t[j][tx] = W[(size_t)(by + j) * E_DIM + bx + tx];
    __syncthreads();
    for (int j = threadIdx.y; j < 32; j += 8) {
        float v = t[tx][j];           // element (k=by+tx, n=bx+j)
        T[(size_t)(bx + j) * E_DIM + by + tx] = __float2half_rn(v);
    }
}

// ============================================================
// 3) 1-product fp16 GEMM: C = Aq @ Bq^T
//    m16n8k16 + ldmatrix + XOR swizzle + 4-stage cp.async, 1 sync/iter
// ============================================================
#define BM 128
#define BN 128
#define BK 32
#define TILE_B 8192                // 128 rows * 64 bytes per operand tile
#define STAGE_B (2*TILE_B)         // Aq, Bq = 16384
#define NSTG 4
#define GEMM_SMEM (NSTG*STAGE_B)   // 65536 -> 2 CTAs/SM

__global__ void __launch_bounds__(256)
gemm_f16_1p(const __half* __restrict__ Aq, const __half* __restrict__ Bq,
            float* __restrict__ C) {
    extern __shared__ uint32_t smem[];

    int tid  = threadIdx.x;
    int warp = tid >> 5, lane = tid & 31;
    int wm = warp & 3, wn = warp >> 2;             // 4 x 2 warps
    int bm = blockIdx.y * BM, bn = blockIdx.x * BN;

    const char* srcs[2] = {
        (const char*)(Aq + (size_t)bm * E_DIM),
        (const char*)(Bq + (size_t)bn * E_DIM) };
    uint32_t sbase = smem_addr(smem);

    auto load_tile = [&](int kt, int stg) {
        uint32_t dst0 = sbase + (uint32_t)stg * STAGE_B;
        int koff = kt * (BK*2);    // byte offset along K
        #pragma unroll
        for (int arr = 0; arr < 2; arr++) {
            #pragma unroll
            for (int i = 0; i < 2; i++) {
                int f = tid + i*256;
                int row = f >> 2, ch = f & 3;
                int sw = ch ^ ((row >> 1) & 3);
                uint32_t dst = dst0 + arr*TILE_B + row*64 + sw*16;
                const char* src = srcs[arr] + (size_t)row * (E_DIM*2) + koff + ch*16;
                CP_ASYNC16(dst, src);
            }
        }
    };

    // ---- ldmatrix lane addresses (ks=0; ks=1 is XOR 32) ----
    int lm = lane & 7, lg = lane >> 3;   // lg = matrix index 0..3
    uint32_t aoff[2];
    #pragma unroll
    for (int mt = 0; mt < 2; mt++) {
        int row = wm*32 + mt*16 + (lg & 1)*8 + lm;
        int swc = (lg >> 1) ^ ((row >> 1) & 3);
        aoff[mt] = (uint32_t)(row*64 + swc*16);
    }
    uint32_t boff[4];
    #pragma unroll
    for (int j = 0; j < 4; j++) {
        int row = wn*64 + j*16 + (lg >> 1)*8 + lm;
        int swc = (lg & 1) ^ ((row >> 1) & 3);
        boff[j] = (uint32_t)(row*64 + swc*16);
    }

    float acc[2][8][4];
    #pragma unroll
    for (int mt = 0; mt < 2; mt++)
        #pragma unroll
        for (int nt = 0; nt < 8; nt++)
            #pragma unroll
            for (int q = 0; q < 4; q++) acc[mt][nt][q] = 0.f;

    const int NK = E_DIM / BK;   // 32
    load_tile(0, 0); CP_COMMIT();
    load_tile(1, 1); CP_COMMIT();
    load_tile(2, 2); CP_COMMIT();

    for (int kt = 0; kt < NK; kt++) {
        int stg = kt % NSTG;
        if (kt == NK - 1) { CP_WAIT(0); } else { CP_WAIT(2); }
        __syncthreads();
        if (kt + 3 < NK) { load_tile(kt + 3, (kt + 3) % NSTG); CP_COMMIT(); }

        uint32_t tA = sbase + (uint32_t)stg * STAGE_B;
        uint32_t tB = tA + TILE_B;

        #pragma unroll
        for (int ks = 0; ks < 2; ks++) {
            uint32_t ksx = (uint32_t)(ks * 32);
            uint32_t aq[2][4], bq[8][2];
            #pragma unroll
            for (int mt = 0; mt < 2; mt++)
                LDSM4(aq[mt], tA + (aoff[mt] ^ ksx));
            #pragma unroll
            for (int j = 0; j < 4; j++) {
                uint32_t rb[4];
                LDSM4(rb, tB + (boff[j] ^ ksx));
                bq[2*j][0] = rb[0]; bq[2*j][1] = rb[1];
                bq[2*j+1][0] = rb[2]; bq[2*j+1][1] = rb[3];
            }
            #pragma unroll
            for (int mt = 0; mt < 2; mt++)
                #pragma unroll
                for (int nt = 0; nt < 8; nt++)
                    mma_f16(acc[mt][nt], aq[mt], bq[nt]);
        }
    }

    #pragma unroll
    for (int mt = 0; mt < 2; mt++) {
        int r0 = bm + wm*32 + mt*16 + (lane >> 2);
        #pragma unroll
        for (int nt = 0; nt < 8; nt++) {
            int c0 = bn + wn*64 + nt*8 + ((lane & 3) << 1);
            *(float2*)(&C[(size_t) r0     *E_DIM + c0]) = make_float2(acc[mt][nt][0], acc[mt][nt][1]);
            *(float2*)(&C[(size_t)(r0 + 8)*E_DIM + c0]) = make_float2(acc[mt][nt][2], acc[mt][nt][3]);
        }
    }
}

// ============================================================
// 4) chunked associative exp-scan
// ============================================================
__global__ void scan_pass1(const float* __restrict__ time_decay) {
    int tid = blockIdx.x * blockDim.x + threadIdx.x;
    int c = tid / CH, ch = tid % CH;
    float w = time_decay[ch & (E_DIM - 1)];
    float a = 0.f, b = 0.f, p = -1e30f;
    int base = c * CLEN;
    for (int t0 = 0; t0 < CLEN; t0 += 8) {
        float kk[8], vv[8];
        #pragma unroll
        for (int i = 0; i < 8; i++) {
            size_t off = (size_t)(base + t0 + i) * CH + ch;
            kk[i] = g_k[off]; vv[i] = g_v[off];
        }
        #pragma unroll
        for (int i = 0; i < 8; i++) {
            float pw = p + w;
            float d  = pw - kk[i];
            float e  = __expf(-fabsf(d));
            float e1 = (d >= 0.f) ? 1.f : e;
            float e2 = (d >= 0.f) ? e   : 1.f;
            a = a*e1 + vv[i]*e2;
            b = b*e1 + e2;
            p = fmaxf(pw, kk[i]);
        }
    }
    g_agg[              c*CH + ch] = a;
    g_agg[  NCHUNK*CH + c*CH + ch] = b;
    g_agg[2*NCHUNK*CH + c*CH + ch] = p;
}

__global__ void scan_pass2(const float* __restrict__ time_decay) {
    int ch = blockIdx.x * blockDim.x + threadIdx.x;
    float w  = time_decay[ch & (E_DIM - 1)];
    float Lw = (float)CLEN * w;
    float a = 0.f, b = 0.f, p = -1e30f;
    for (int c = 0; c < NCHUNK; c++) {
        g_pre[              c*CH + ch] = a;
        g_pre[  NCHUNK*CH + c*CH + ch] = b;
        g_pre[2*NCHUNK*CH + c*CH + ch] = p;
        float a2 = g_agg[              c*CH + ch];
        float b2 = g_agg[  NCHUNK*CH + c*CH + ch];
        float p2 = g_agg[2*NCHUNK*CH + c*CH + ch];
        float pw = p + Lw;
        float d  = pw - p2;
        float e  = __expf(-fabsf(d));
        float e1 = (d >= 0.f) ? 1.f : e;
        float e2 = (d >= 0.f) ? e   : 1.f;
        a = a*e1 + a2*e2;
        b = b*e1 + b2*e2;
        p = fmaxf(pw, p2);
    }
}

__global__ void scan_pass3(const float* __restrict__ time_decay,
                           const float* __restrict__ time_first) {
    int tid = blockIdx.x * blockDim.x + threadIdx.x;
    int c = tid / CH, ch = tid % CH;
    int e0 = ch & (E_DIM - 1);
    float w = time_decay[e0];
    float u = time_first[e0];
    float a = g_pre[              c*CH + ch];
    float b = g_pre[  NCHUNK*CH + c*CH + ch];
    float p = g_pre[2*NCHUNK*CH + c*CH + ch];
    int base = c * CLEN;
    for (int t0 = 0; t0 < CLEN; t0 += 8) {
        float kk[8], vv[8];
        #pragma unroll
        for (int i = 0; i < 8; i++) {
            size_t off = (size_t)(base + t0 + i) * CH + ch;
            kk[i] = g_k[off]; vv[i] = g_v[off];
        }
        #pragma unroll
        for (int i = 0; i < 8; i++) {
            float pw = p + w;
            float d  = pw - kk[i];
            float e  = __expf(-fabsf(d));
            float e1 = (d >= 0.f) ? 1.f : e;
            float e2 = (d >= 0.f) ? e   : 1.f;
            a = a*e1 + vv[i]*e2;
            b = b*e1 + e2;
            p = fmaxf(pw, kk[i]);
            float kb = kk[i] + u + w;
            float d2 = p - kb;
            float eo = __expf(-fabsf(d2));
            float o1 = (d2 >= 0.f) ? 1.f : eo;
            float o2 = (d2 >= 0.f) ? eo  : 1.f;
            float cn = a*o1 + vv[i]*o2;
            float dn = b*o1 + o2;
            float q  = __fdividef(cn, dn);
            size_t off = (size_t)(base + t0 + i) * CH + ch;
            g_r[off] = __float2half_rn(q);
        }
    }
}

// ============================================================
// launch
// ============================================================
extern "C" void kernel_launch(void* const* d_in, const int* in_sizes, int n_in,
                              void* d_out, int out_size) {
    const float* x     = (const float*)d_in[0];
    const float* tmrkv = (const float*)d_in[1];
    const float* Wk    = (const float*)d_in[2];
    const float* Wv    = (const float*)d_in[3];
    const float* td    = (const float*)d_in[4];
    const float* tf    = (const float*)d_in[5];
    const float* Wout  = (const float*)d_in[6];
    float* out = (float*)d_out;

    cudaFuncSetAttribute(gemm_f16_1p,
                         cudaFuncAttributeMaxDynamicSharedMemorySize, GEMM_SMEM);

    __half *p_xk, *p_xv, *p_r, *p_wk, *p_wv, *p_wo;
    float *p_k, *p_v;
    cudaGetSymbolAddress((void**)&p_xk, g_xk);
    cudaGetSymbolAddress((void**)&p_xv, g_xv);
    cudaGetSymbolAddress((void**)&p_r,  g_r);
    cudaGetSymbolAddress((void**)&p_wk, g_wkt);
    cudaGetSymbolAddress((void**)&p_wv, g_wvt);
    cudaGetSymbolAddress((void**)&p_wo, g_wot);
    cudaGetSymbolAddress((void**)&p_k,  g_k);
    cudaGetSymbolAddress((void**)&p_v,  g_v);

    // 1) mix + quantize
    mix_quant_kernel<<<(M_TOT*E_DIM/4)/256, 256>>>(x, tmrkv);

    // 2) weight transpose + quantize
    dim3 wgrid(32, 32), wblk(32, 8);
    wsplit_kernel<<<wgrid, wblk>>>(Wk,   p_wk);
    wsplit_kernel<<<wgrid, wblk>>>(Wv,   p_wv);
    wsplit_kernel<<<wgrid, wblk>>>(Wout, p_wo);

    // 3) k = xk @ Wk ; v = xv @ Wv
    dim3 ggrid(E_DIM/BN, M_TOT/BM);
    gemm_f16_1p<<<ggrid, 256, GEMM_SMEM>>>(p_xk, p_wk, p_k);
    gemm_f16_1p<<<ggrid, 256, GEMM_SMEM>>>(p_xv, p_wv, p_v);

    // 4) scan
    scan_pass1<<<(NCHUNK*CH)/256, 256>>>(td);
    scan_pass2<<<CH/256, 256>>>(td);
    scan_pass3<<<(NCHUNK*CH)/256, 256>>>(td, tf);

    // 5) out = rwkv @ Wout
    gemm_f16_1p<<<ggrid, 256, GEMM_SMEM>>>(p_r, p_wo, out);
}

// round 9
// speedup vs baseline: 2.3354x; 1.0180x over previous
#include <cuda_runtime.h>
#include <cuda_fp16.h>
#include <cstdint>
#include <cstddef>

#define S_LEN 2048
#define B_DIM 8
#define E_DIM 1024
#define M_TOT (S_LEN*B_DIM)      // 16384
#define CH    (B_DIM*E_DIM)      // 8192
#define NCHUNK 64
#define CLEN  (S_LEN/NCHUNK)     // 32
#define CH4   (CH/4)             // 2048

// ---------------- scratch (device globals; no allocation allowed) ------------
__device__ __half g_xk[(size_t)M_TOT*E_DIM];
__device__ __half g_xv[(size_t)M_TOT*E_DIM];
__device__ __half g_r [(size_t)M_TOT*E_DIM];
__device__ float g_k [(size_t)M_TOT*E_DIM];
__device__ float g_v [(size_t)M_TOT*E_DIM];
__device__ __half g_wkt[(size_t)E_DIM*E_DIM];
__device__ __half g_wvt[(size_t)E_DIM*E_DIM];
__device__ __half g_wot[(size_t)E_DIM*E_DIM];
__device__ float g_agg[3*NCHUNK*CH];
__device__ float g_pre[3*NCHUNK*CH];

// ---------------- helpers ----------------------------------------------------
__device__ __forceinline__ uint32_t smem_addr(const void* p) {
    uint32_t a;
    asm("{ .reg .u64 t; cvta.to.shared.u64 t, %1; cvt.u32.u64 %0, t; }" : "=r"(a) : "l"(p));
    return a;
}
#define CP_ASYNC16(dst, src) \
    asm volatile("cp.async.cg.shared.global [%0], [%1], 16;" :: "r"(dst), "l"(src) : "memory")
#define CP_COMMIT() asm volatile("cp.async.commit_group;" ::: "memory")
#define CP_WAIT(n)  asm volatile("cp.async.wait_group %0;" :: "n"(n) : "memory")

#define LDSM4(r, addr) \
    asm volatile("ldmatrix.sync.aligned.m8n8.x4.shared.b16 {%0,%1,%2,%3}, [%4];" \
        : "=r"((r)[0]), "=r"((r)[1]), "=r"((r)[2]), "=r"((r)[3]) : "r"(addr))

__device__ __forceinline__ void mma_f16(float c[4], const uint32_t a[4], const uint32_t b[2]) {
    asm volatile(
        "mma.sync.aligned.m16n8k16.row.col.f32.f16.f16.f32 "
        "{%0,%1,%2,%3}, {%4,%5,%6,%7}, {%8,%9}, {%0,%1,%2,%3};\n"
        : "+f"(c[0]), "+f"(c[1]), "+f"(c[2]), "+f"(c[3])
        : "r"(a[0]), "r"(a[1]), "r"(a[2]), "r"(a[3]), "r"(b[0]), "r"(b[1]));
}

// ============================================================
// 1) fused prep: token mix + fp16 quantize  AND  3x weight transpose
//    blocks [0, MIXB)            -> mix
//    blocks [MIXB, MIXB+3*1024)  -> wsplit (1024 blocks per weight)
// ============================================================
#define MIXB (M_TOT*E_DIM/4/256)   // 16384

__global__ void prep_kernel(const float* __restrict__ x,
                            const float* __restrict__ tmrkv,
                            const float* __restrict__ Wk,
                            const float* __restrict__ Wv,
                            const float* __restrict__ Wout) {
    __shared__ float t[32][33];
    int blk = blockIdx.x;
    int tid = threadIdx.x;

    if (blk < MIXB) {
        // ---- mix + quantize ----
        int i4  = blk * 256 + tid;
        int idx = i4 * 4;
        int e   = idx & (E_DIM - 1);
        float4 xc = *(const float4*)(x + idx);
        float4 xp = make_float4(0.f, 0.f, 0.f, 0.f);
        if (idx >= CH) xp = *(const float4*)(x + idx - CH);
        float4 mk = *(const float4*)(tmrkv + E_DIM   + e);
        float4 mv = *(const float4*)(tmrkv + 2*E_DIM + e);
        float ok[4], ov[4];
        ok[0] = mk.x*xc.x + (1.f-mk.x)*xp.x;  ov[0] = mv.x*xc.x + (1.f-mv.x)*xp.x;
        ok[1] = mk.y*xc.y + (1.f-mk.y)*xp.y;  ov[1] = mv.y*xc.y + (1.f-mv.y)*xp.y;
        ok[2] = mk.z*xc.z + (1.f-mk.z)*xp.z;  ov[2] = mv.z*xc.z + (1.f-mv.z)*xp.z;
        ok[3] = mk.w*xc.w + (1.f-mk.w)*xp.w;  ov[3] = mv.w*xc.w + (1.f-mv.w)*xp.w;
        ushort4 kq, vq;
        kq.x = __half_as_ushort(__float2half_rn(ok[0]));
        kq.y = __half_as_ushort(__float2half_rn(ok[1]));
        kq.z = __half_as_ushort(__float2half_rn(ok[2]));
        kq.w = __half_as_ushort(__float2half_rn(ok[3]));
        vq.x = __half_as_ushort(__float2half_rn(ov[0]));
        vq.y = __half_as_ushort(__float2half_rn(ov[1]));
        vq.z = __half_as_ushort(__float2half_rn(ov[2]));
        vq.w = __half_as_ushort(__float2half_rn(ov[3]));
        *(ushort4*)((unsigned short*)g_xk + idx) = kq;
        *(ushort4*)((unsigned short*)g_xv + idx) = vq;
    } else {
        // ---- weight transpose + quantize ----
        int wb   = blk - MIXB;
        int widx = wb >> 10;          // 0,1,2
        int tb   = wb & 1023;
        const float* W = (widx == 0) ? Wk : (widx == 1) ? Wv : Wout;
        __half* T = (widx == 0) ? g_wkt : (widx == 1) ? g_wvt : g_wot;
        int bx = (tb & 31) * 32;      // n block
        int by = (tb >> 5) * 32;      // k block
        int tx = tid & 31, ty = tid >> 5;   // 32 x 8
        for (int j = ty; j < 32; j += 8)
            t[j][tx] = W[(size_t)(by + j) * E_DIM + bx + tx];
        __syncthreads();
        for (int j = ty; j < 32; j += 8) {
            float v = t[tx][j];       // element (k=by+tx, n=bx+j)
            T[(size_t)(bx + j) * E_DIM + by + tx] = __float2half_rn(v);
        }
    }
}

// ============================================================
// 2) 1-product fp16 GEMM: C = Aq @ Bq^T
//    m16n8k16 + ldmatrix + XOR swizzle + 4-stage cp.async, 1 sync/iter
// ============================================================
#define BM 128
#define BN 128
#define BK 32
#define TILE_B 8192                // 128 rows * 64 bytes per operand tile
#define STAGE_B (2*TILE_B)         // Aq, Bq = 16384
#define NSTG 4
#define GEMM_SMEM (NSTG*STAGE_B)   // 65536 -> 2 CTAs/SM

__global__ void __launch_bounds__(256)
gemm_f16_1p(const __half* __restrict__ Aq, const __half* __restrict__ Bq,
            float* __restrict__ C) {
    extern __shared__ uint32_t smem[];

    int tid  = threadIdx.x;
    int warp = tid >> 5, lane = tid & 31;
    int wm = warp & 3, wn = warp >> 2;             // 4 x 2 warps
    int bm = blockIdx.y * BM, bn = blockIdx.x * BN;

    const char* srcs[2] = {
        (const char*)(Aq + (size_t)bm * E_DIM),
        (const char*)(Bq + (size_t)bn * E_DIM) };
    uint32_t sbase = smem_addr(smem);

    auto load_tile = [&](int kt, int stg) {
        uint32_t dst0 = sbase + (uint32_t)stg * STAGE_B;
        int koff = kt * (BK*2);    // byte offset along K
        #pragma unroll
        for (int arr = 0; arr < 2; arr++) {
            #pragma unroll
            for (int i = 0; i < 2; i++) {
                int f = tid + i*256;
                int row = f >> 2, ch = f & 3;
                int sw = ch ^ ((row >> 1) & 3);
                uint32_t dst = dst0 + arr*TILE_B + row*64 + sw*16;
                const char* src = srcs[arr] + (size_t)row * (E_DIM*2) + koff + ch*16;
                CP_ASYNC16(dst, src);
            }
        }
    };

    int lm = lane & 7, lg = lane >> 3;   // lg = matrix index 0..3
    uint32_t aoff[2];
    #pragma unroll
    for (int mt = 0; mt < 2; mt++) {
        int row = wm*32 + mt*16 + (lg & 1)*8 + lm;
        int swc = (lg >> 1) ^ ((row >> 1) & 3);
        aoff[mt] = (uint32_t)(row*64 + swc*16);
    }
    uint32_t boff[4];
    #pragma unroll
    for (int j = 0; j < 4; j++) {
        int row = wn*64 + j*16 + (lg >> 1)*8 + lm;
        int swc = (lg & 1) ^ ((row >> 1) & 3);
        boff[j] = (uint32_t)(row*64 + swc*16);
    }

    float acc[2][8][4];
    #pragma unroll
    for (int mt = 0; mt < 2; mt++)
        #pragma unroll
        for (int nt = 0; nt < 8; nt++)
            #pragma unroll
            for (int q = 0; q < 4; q++) acc[mt][nt][q] = 0.f;

    const int NK = E_DIM / BK;   // 32
    load_tile(0, 0); CP_COMMIT();
    load_tile(1, 1); CP_COMMIT();
    load_tile(2, 2); CP_COMMIT();

    for (int kt = 0; kt < NK; kt++) {
        int stg = kt % NSTG;
        if (kt == NK - 1) { CP_WAIT(0); } else { CP_WAIT(2); }
        __syncthreads();
        if (kt + 3 < NK) { load_tile(kt + 3, (kt + 3) % NSTG); CP_COMMIT(); }

        uint32_t tA = sbase + (uint32_t)stg * STAGE_B;
        uint32_t tB = tA + TILE_B;

        #pragma unroll
        for (int ks = 0; ks < 2; ks++) {
            uint32_t ksx = (uint32_t)(ks * 32);
            uint32_t aq[2][4], bq[8][2];
            #pragma unroll
            for (int mt = 0; mt < 2; mt++)
                LDSM4(aq[mt], tA + (aoff[mt] ^ ksx));
            #pragma unroll
            for (int j = 0; j < 4; j++) {
                uint32_t rb[4];
                LDSM4(rb, tB + (boff[j] ^ ksx));
                bq[2*j][0] = rb[0]; bq[2*j][1] = rb[1];
                bq[2*j+1][0] = rb[2]; bq[2*j+1][1] = rb[3];
            }
            #pragma unroll
            for (int mt = 0; mt < 2; mt++)
                #pragma unroll
                for (int nt = 0; nt < 8; nt++)
                    mma_f16(acc[mt][nt], aq[mt], bq[nt]);
        }
    }

    #pragma unroll
    for (int mt = 0; mt < 2; mt++) {
        int r0 = bm + wm*32 + mt*16 + (lane >> 2);
        #pragma unroll
        for (int nt = 0; nt < 8; nt++) {
            int c0 = bn + wn*64 + nt*8 + ((lane & 3) << 1);
            *(float2*)(&C[(size_t) r0     *E_DIM + c0]) = make_float2(acc[mt][nt][0], acc[mt][nt][1]);
            *(float2*)(&C[(size_t)(r0 + 8)*E_DIM + c0]) = make_float2(acc[mt][nt][2], acc[mt][nt][3]);
        }
    }
}

// ============================================================
// 3) chunked associative exp-scan (float4 across channels)
// ============================================================
__device__ __forceinline__ void scan_step(float& a, float& b, float& p,
                                          float w, float k, float v) {
    float pw = p + w;
    float d  = pw - k;
    float e  = __expf(-fabsf(d));
    float e1 = (d >= 0.f) ? 1.f : e;
    float e2 = (d >= 0.f) ? e   : 1.f;
    a = a*e1 + v*e2;
    b = b*e1 + e2;
    p = fmaxf(pw, k);
}

__global__ void scan_pass1(const float* __restrict__ time_decay) {
    int tid = blockIdx.x * blockDim.x + threadIdx.x;   // NCHUNK*CH4 threads
    int c = tid >> 11, ch4 = tid & (CH4 - 1);
    int ch = ch4 * 4;
    int e  = ch & (E_DIM - 1);
    float4 w4 = *(const float4*)(time_decay + e);
    float a[4] = {0.f,0.f,0.f,0.f}, b[4] = {0.f,0.f,0.f,0.f};
    float p[4] = {-1e30f,-1e30f,-1e30f,-1e30f};
    float wv[4] = {w4.x, w4.y, w4.z, w4.w};
    int base = c * CLEN;
    for (int t0 = 0; t0 < CLEN; t0 += 4) {
        float4 kk[4], vv[4];
        #pragma unroll
        for (int i = 0; i < 4; i++) {
            size_t off = (size_t)(base + t0 + i) * CH + ch;
            kk[i] = *(const float4*)(g_k + off);
            vv[i] = *(const float4*)(g_v + off);
        }
        #pragma unroll
        for (int i = 0; i < 4; i++) {
            scan_step(a[0], b[0], p[0], wv[0], kk[i].x, vv[i].x);
            scan_step(a[1], b[1], p[1], wv[1], kk[i].y, vv[i].y);
            scan_step(a[2], b[2], p[2], wv[2], kk[i].z, vv[i].z);
            scan_step(a[3], b[3], p[3], wv[3], kk[i].w, vv[i].w);
        }
    }
    *(float4*)(g_agg +               c*CH + ch) = make_float4(a[0],a[1],a[2],a[3]);
    *(float4*)(g_agg +   NCHUNK*CH + c*CH + ch) = make_float4(b[0],b[1],b[2],b[3]);
    *(float4*)(g_agg + 2*NCHUNK*CH + c*CH + ch) = make_float4(p[0],p[1],p[2],p[3]);
}

__global__ void scan_pass2(const float* __restrict__ time_decay) {
    int ch = blockIdx.x * blockDim.x + threadIdx.x;
    float w  = time_decay[ch & (E_DIM - 1)];
    float Lw = (float)CLEN * w;
    float a = 0.f, b = 0.f, p = -1e30f;
    for (int c = 0; c < NCHUNK; c++) {
        g_pre[              c*CH + ch] = a;
        g_pre[  NCHUNK*CH + c*CH + ch] = b;
        g_pre[2*NCHUNK*CH + c*CH + ch] = p;
        float a2 = g_agg[              c*CH + ch];
        float b2 = g_agg[  NCHUNK*CH + c*CH + ch];
        float p2 = g_agg[2*NCHUNK*CH + c*CH + ch];
        float pw = p + Lw;
        float d  = pw - p2;
        float e  = __expf(-fabsf(d));
        float e1 = (d >= 0.f) ? 1.f : e;
        float e2 = (d >= 0.f) ? e   : 1.f;
        a = a*e1 + a2*e2;
        b = b*e1 + b2*e2;
        p = fmaxf(pw, p2);
    }
}

__global__ void scan_pass3(const float* __restrict__ time_decay,
                           const float* __restrict__ time_first) {
    int tid = blockIdx.x * blockDim.x + threadIdx.x;
    int c = tid >> 11, ch4 = tid & (CH4 - 1);
    int ch = ch4 * 4;
    int e  = ch & (E_DIM - 1);
    float4 w4 = *(const float4*)(time_decay + e);
    float4 u4 = *(const float4*)(time_first + e);
    float wv[4] = {w4.x, w4.y, w4.z, w4.w};
    float uv[4] = {u4.x, u4.y, u4.z, u4.w};
    float4 a4 = *(const float4*)(g_pre +               c*CH + ch);
    float4 b4 = *(const float4*)(g_pre +   NCHUNK*CH + c*CH + ch);
    float4 p4 = *(const float4*)(g_pre + 2*NCHUNK*CH + c*CH + ch);
    float a[4] = {a4.x,a4.y,a4.z,a4.w};
    float b[4] = {b4.x,b4.y,b4.z,b4.w};
    float p[4] = {p4.x,p4.y,p4.z,p4.w};
    int base = c * CLEN;
    for (int t0 = 0; t0 < CLEN; t0 += 4) {
        float4 kk[4], vv[4];
        #pragma unroll
        for (int i = 0; i < 4; i++) {
            size_t off = (size_t)(base + t0 + i) * CH + ch;
            kk[i] = *(const float4*)(g_k + off);
            vv[i] = *(const float4*)(g_v + off);
        }
        #pragma unroll
        for (int i = 0; i < 4; i++) {
            float kv[4] = {kk[i].x, kk[i].y, kk[i].z, kk[i].w};
            float vvv[4] = {vv[i].x, vv[i].y, vv[i].z, vv[i].w};
            ushort4 outq;
            unsigned short qs[4];
            #pragma unroll
            for (int j = 0; j < 4; j++) {
                scan_step(a[j], b[j], p[j], wv[j], kv[j], vvv[j]);
                float kb = kv[j] + uv[j] + wv[j];
                float d2 = p[j] - kb;
                float eo = __expf(-fabsf(d2));
                float o1 = (d2 >= 0.f) ? 1.f : eo;
                float o2 = (d2 >= 0.f) ? eo  : 1.f;
                float cn = a[j]*o1 + vvv[j]*o2;
                float dn = b[j]*o1 + o2;
                qs[j] = __half_as_ushort(__float2half_rn(__fdividef(cn, dn)));
            }
            outq.x = qs[0]; outq.y = qs[1]; outq.z = qs[2]; outq.w = qs[3];
            size_t off = (size_t)(base + t0 + i) * CH + ch;
            *(ushort4*)((unsigned short*)g_r + off) = outq;
        }
    }
}

// ============================================================
// launch
// ============================================================
extern "C" void kernel_launch(void* const* d_in, const int* in_sizes, int n_in,
                              void* d_out, int out_size) {
    const float* x     = (const float*)d_in[0];
    const float* tmrkv = (const float*)d_in[1];
    const float* Wk    = (const float*)d_in[2];
    const float* Wv    = (const float*)d_in[3];
    const float* td    = (const float*)d_in[4];
    const float* tf    = (const float*)d_in[5];
    const float* Wout  = (const float*)d_in[6];
    float* out = (float*)d_out;

    cudaFuncSetAttribute(gemm_f16_1p,
                         cudaFuncAttributeMaxDynamicSharedMemorySize, GEMM_SMEM);

    __half *p_xk, *p_xv, *p_r, *p_wk, *p_wv, *p_wo;
    float *p_k, *p_v;
    cudaGetSymbolAddress((void**)&p_xk, g_xk);
    cudaGetSymbolAddress((void**)&p_xv, g_xv);
    cudaGetSymbolAddress((void**)&p_r,  g_r);
    cudaGetSymbolAddress((void**)&p_wk, g_wkt);
    cudaGetSymbolAddress((void**)&p_wv, g_wvt);
    cudaGetSymbolAddress((void**)&p_wo, g_wot);
    cudaGetSymbolAddress((void**)&p_k,  g_k);
    cudaGetSymbolAddress((void**)&p_v,  g_v);

    // 1) fused prep: mix + 3x weight transpose
    prep_kernel<<<MIXB + 3*1024, 256>>>(x, tmrkv, Wk, Wv, Wout);

    // 2) k = xk @ Wk ; v = xv @ Wv
    dim3 ggrid(E_DIM/BN, M_TOT/BM);
    gemm_f16_1p<<<ggrid, 256, GEMM_SMEM>>>(p_xk, p_wk, p_k);
    gemm_f16_1p<<<ggrid, 256, GEMM_SMEM>>>(p_xv, p_wv, p_v);

    // 3) scan
    scan_pass1<<<(NCHUNK*CH4)/256, 256>>>(td);
    scan_pass2<<<CH/256, 256>>>(td);
    scan_pass3<<<(NCHUNK*CH4)/256, 256>>>(td, tf);

    // 4) out = rwkv @ Wout
    gemm_f16_1p<<<ggrid, 256, GEMM_SMEM>>>(p_r, p_wo, out);
}